// round 3
// baseline (speedup 1.0000x reference)
#include <cuda_runtime.h>
#include <cstdint>

// ---------------- problem constants -------------------------------------
#define B_    4
#define S_    8192
#define D_    2048
#define HD_   128
#define NTOK  (B_ * S_)            // 32768 tokens
#define NCOL  512                  // 4 projections * HD
#define NBLK  (B_ * (S_ / 4))      // 8192 output blocks
#define OUT_ELEMS (NBLK * HD_)     // 1048576

// GEMM tiling
#define BM 128
#define BN 128
#define BK 64
#define NKC (D_ / BK)              // 32 k-chunks

// fixed-point scales
#define SA 2040.0f                 // h scale  (covers |h| <= 7.97)
#define SB 100000.0f               // w scale  (covers |w| <= 0.1625)
#define INV_SCALE (1.0f / (2040.0f * 100000.0f))

// ---------------- scratch (static device globals) ------------------------
__device__ signed char g_B1[NCOL * D_];           // 1 MB hi digits, K-major
__device__ signed char g_B0[NCOL * D_];           // 1 MB lo digits, K-major
__device__ float g_C[(size_t)NTOK * NCOL];        // 64 MB GEMM output

// ---------------- helpers ------------------------------------------------
__device__ __forceinline__ uint32_t smem_to_u32(const void* p) {
    uint32_t a;
    asm("{ .reg .u64 t; cvta.to.shared.u64 t, %1; cvt.u32.u64 %0, t; }"
        : "=r"(a) : "l"(p));
    return a;
}

#define CP_ASYNC16(dst_u32, src_ptr) \
    asm volatile("cp.async.cg.shared.global [%0], [%1], 16;" \
                 :: "r"(dst_u32), "l"(src_ptr) : "memory")
#define CP_ASYNC_COMMIT() asm volatile("cp.async.commit_group;" ::: "memory")
#define CP_ASYNC_WAIT0()  asm volatile("cp.async.wait_group 0;" ::: "memory")

#define IMMA(d, a, b) \
    asm volatile("mma.sync.aligned.m16n8k32.row.col.s32.s8.s8.s32 " \
                 "{%0,%1,%2,%3}, {%4,%5,%6,%7}, {%8,%9}, {%0,%1,%2,%3};" \
                 : "+r"((d)[0]), "+r"((d)[1]), "+r"((d)[2]), "+r"((d)[3]) \
                 : "r"((a)[0]), "r"((a)[1]), "r"((a)[2]), "r"((a)[3]), \
                   "r"((b)[0]), "r"((b)[1]))

// digit split of an s32 value in [-16256, 16255]: v = 128*hi + lo, hi/lo in s8
__device__ __forceinline__ void digsplit(int a, int& hi, int& lo) {
    a = a < -16256 ? -16256 : (a > 16255 ? 16255 : a);
    hi = (a + 64) >> 7;
    lo = a - (hi << 7);
}

// quantize 4 floats (scale SA) into packed hi/lo digit bytes
__device__ __forceinline__ void quant4(float4 v, uint32_t& p1, uint32_t& p0) {
    int ai[4] = { __float2int_rn(v.x * SA), __float2int_rn(v.y * SA),
                  __float2int_rn(v.z * SA), __float2int_rn(v.w * SA) };
    uint32_t r1 = 0, r0 = 0;
    #pragma unroll
    for (int j = 0; j < 4; ++j) {
        int hi, lo;
        digsplit(ai[j], hi, lo);
        r1 |= (uint32_t)(hi & 255) << (8 * j);
        r0 |= (uint32_t)(lo & 255) << (8 * j);
    }
    p1 = r1; p0 = r0;
}

// ---------------- smem layout (bytes), padded 80B rows -------------------
#define ROWB   80
#define PLANE  (128 * ROWB)        // 10240 B
#define OFF_A1 0
#define OFF_A0 PLANE
#define OFF_B1 (2 * PLANE)
#define OFF_B0 (3 * PLANE)
#define STAGE  (4 * PLANE)         // 40960 B
#define SMEM_BYTES (2 * STAGE)     // 81920 B

// ---------------- kernel 1: weight quantize + transpose ------------------
__global__ void prep_w_kernel(const float* __restrict__ wka,
                              const float* __restrict__ wkb,
                              const float* __restrict__ wza,
                              const float* __restrict__ wzb)
{
    int k = blockIdx.x * blockDim.x + threadIdx.x;   // 0..2047
    int n = blockIdx.y;                              // 0..511
    const float* w = (n < 128) ? wka : (n < 256) ? wkb : (n < 384) ? wza : wzb;
    int j = n & 127;
    float x = w[(size_t)k * HD_ + j];
    int bi = __float2int_rn(x * SB);
    int hi, lo;
    digsplit(bi, hi, lo);
    g_B1[(size_t)n * D_ + k] = (signed char)hi;
    g_B0[(size_t)n * D_ + k] = (signed char)lo;
}

// ---------------- kernel 2: pipelined IMMA 3-pass GEMM -------------------
// C[t, 0:512] = h[t, :] @ [Wkva | Wkvb | Wza | Wzb]
__global__ void __launch_bounds__(512, 1)
gemm_kernel(const float* __restrict__ h)
{
    extern __shared__ char sm[];
    const uint32_t smem_base = smem_to_u32(sm);

    const int tid    = threadIdx.x;
    const int lane   = tid & 31;
    const int wid    = tid >> 5;
    const int warp_m = wid >> 2;          // 0..3  (32 rows each)
    const int warp_n = wid & 3;           // 0..3  (32 cols each)

    const int t0 = (int)(blockIdx.x >> 2) * BM;
    const int n0 = (int)(blockIdx.x & 3) * BN;

    // tile-load coordinates: one 16-float (=16B digit) slot per thread
    const int arow = tid >> 2;            // 0..127
    const int ac4  = tid & 3;             // 16B chunk within 64B row

    const float*       hrow  = h + (size_t)(t0 + arow) * D_ + ac4 * 16;
    const signed char* b1row = g_B1 + (size_t)(n0 + arow) * D_ + ac4 * 16;
    const signed char* b0row = g_B0 + (size_t)(n0 + arow) * D_ + ac4 * 16;
    const uint32_t sts_off = (uint32_t)(arow * ROWB + ac4 * 16);

    // -------- prologue: stage 0 --------
    float4 v[4];
    {
        #pragma unroll
        for (int i = 0; i < 4; ++i) v[i] = *(const float4*)(hrow + i * 4);
        CP_ASYNC16(smem_base + OFF_B1 + sts_off, b1row);
        CP_ASYNC16(smem_base + OFF_B0 + sts_off, b0row);
        CP_ASYNC_COMMIT();
        uint4 q1, q0;
        quant4(v[0], q1.x, q0.x); quant4(v[1], q1.y, q0.y);
        quant4(v[2], q1.z, q0.z); quant4(v[3], q1.w, q0.w);
        *(uint4*)(sm + OFF_A1 + sts_off) = q1;
        *(uint4*)(sm + OFF_A0 + sts_off) = q0;
        CP_ASYNC_WAIT0();
        __syncthreads();
    }

    int P11[2][4][4], Pmid[2][4][4];
    #pragma unroll
    for (int mt = 0; mt < 2; ++mt)
        #pragma unroll
        for (int nt = 0; nt < 4; ++nt)
            #pragma unroll
            for (int i = 0; i < 4; ++i) { P11[mt][nt][i] = 0; Pmid[mt][nt][i] = 0; }

    const int fr = lane >> 2;            // fragment row within 8
    const int fc = (lane & 3) * 4;       // fragment k-byte offset

    for (int c = 0; c < NKC; ++c) {
        const int sb = (c & 1) * STAGE;
        const int nb = sb ^ STAGE;

        if (c + 1 < NKC) {
            const int k1 = (c + 1) * BK;
            #pragma unroll
            for (int i = 0; i < 4; ++i) v[i] = *(const float4*)(hrow + k1 + i * 4);
            CP_ASYNC16(smem_base + nb + OFF_B1 + sts_off, b1row + k1);
            CP_ASYNC16(smem_base + nb + OFF_B0 + sts_off, b0row + k1);
            CP_ASYNC_COMMIT();
        }

        // -------- compute on stage sb: 2 k32-steps --------
        #pragma unroll
        for (int ks = 0; ks < 2; ++ks) {
            const int kb = ks * 32 + fc;
            int aH[2][4], aL[2][4], bH[4][2], bL[4][2];
            #pragma unroll
            for (int mt = 0; mt < 2; ++mt) {
                const char* p1 = sm + sb + OFF_A1 + (warp_m * 32 + mt * 16 + fr) * ROWB + kb;
                const char* p0 = sm + sb + OFF_A0 + (warp_m * 32 + mt * 16 + fr) * ROWB + kb;
                aH[mt][0] = *(const int*)(p1);
                aH[mt][1] = *(const int*)(p1 + 8 * ROWB);
                aH[mt][2] = *(const int*)(p1 + 16);
                aH[mt][3] = *(const int*)(p1 + 8 * ROWB + 16);
                aL[mt][0] = *(const int*)(p0);
                aL[mt][1] = *(const int*)(p0 + 8 * ROWB);
                aL[mt][2] = *(const int*)(p0 + 16);
                aL[mt][3] = *(const int*)(p0 + 8 * ROWB + 16);
            }
            #pragma unroll
            for (int nt = 0; nt < 4; ++nt) {
                const char* p1 = sm + sb + OFF_B1 + (warp_n * 32 + nt * 8 + fr) * ROWB + kb;
                const char* p0 = sm + sb + OFF_B0 + (warp_n * 32 + nt * 8 + fr) * ROWB + kb;
                bH[nt][0] = *(const int*)(p1);
                bH[nt][1] = *(const int*)(p1 + 16);
                bL[nt][0] = *(const int*)(p0);
                bL[nt][1] = *(const int*)(p0 + 16);
            }
            #pragma unroll
            for (int mt = 0; mt < 2; ++mt)
                #pragma unroll
                for (int nt = 0; nt < 4; ++nt) {
                    IMMA(P11[mt][nt],  aH[mt], bH[nt]);
                    IMMA(Pmid[mt][nt], aH[mt], bL[nt]);
                    IMMA(Pmid[mt][nt], aL[mt], bH[nt]);
                }
        }

        if (c + 1 < NKC) {
            uint4 q1, q0;
            quant4(v[0], q1.x, q0.x); quant4(v[1], q1.y, q0.y);
            quant4(v[2], q1.z, q0.z); quant4(v[3], q1.w, q0.w);
            *(uint4*)(sm + nb + OFF_A1 + sts_off) = q1;
            *(uint4*)(sm + nb + OFF_A0 + sts_off) = q0;
            CP_ASYNC_WAIT0();
        }
        __syncthreads();
    }

    // -------- writeback: exact s64 digit combine, then scale -------------
    #pragma unroll
    for (int mt = 0; mt < 2; ++mt) {
        int r0 = t0 + warp_m * 32 + mt * 16 + fr;
        #pragma unroll
        for (int nt = 0; nt < 4; ++nt) {
            int cb = n0 + warp_n * 32 + nt * 8 + (lane & 3) * 2;
            float cv[4];
            #pragma unroll
            for (int i = 0; i < 4; ++i) {
                long long tot = ((long long)P11[mt][nt][i] << 14)
                              + ((long long)Pmid[mt][nt][i] << 7);
                cv[i] = (float)tot * INV_SCALE;
            }
            *(float2*)(g_C + (size_t)r0 * NCOL + cb)       = make_float2(cv[0], cv[1]);
            *(float2*)(g_C + (size_t)(r0 + 8) * NCOL + cb) = make_float2(cv[2], cv[3]);
        }
    }
}

// ---------------- kernel 3: masked softmax compression -------------------
// C columns: [0,128)=c_a, [128,256)=c_b, [256,384)=z_a, [384,512)=z_b
__global__ void epilogue_kernel(const float* __restrict__ b_a,
                                const float* __restrict__ b_b,
                                float* __restrict__ out, int dup)
{
    int g  = blockIdx.x * blockDim.x + threadIdx.x;   // 0..1048575
    int d  = g & 127;
    int bi = g >> 7;           // global block id 0..8191
    int i  = bi & 2047;        // block within batch
    int b  = bi >> 11;         // batch
    int t0 = b * S_ + i * 4;   // first token of current block

    float logit[8], val[8];
    const bool has_prev = (i > 0);
    #pragma unroll
    for (int j = 0; j < 4; ++j) {
        if (has_prev) {
            const float* Cp = g_C + (size_t)(t0 - 4 + j) * NCOL;
            logit[j] = Cp[384 + d] + b_b[j * 128 + d];
            val[j]   = Cp[128 + d];
        } else {
            logit[j] = -3.0e38f;
            val[j]   = 0.0f;
        }
        const float* Cc = g_C + (size_t)(t0 + j) * NCOL;
        logit[4 + j] = Cc[256 + d] + b_a[j * 128 + d];
        val[4 + j]   = Cc[d];
    }
    float mx = logit[0];
    #pragma unroll
    for (int j = 1; j < 8; ++j) mx = fmaxf(mx, logit[j]);
    float s = 0.0f, acc = 0.0f;
    #pragma unroll
    for (int j = 0; j < 8; ++j) {
        float e = __expf(logit[j] - mx);
        s   += e;
        acc += e * val[j];
    }
    float r = acc / s;
    out[g] = r;
    if (dup) out[g + OUT_ELEMS] = r;
}

// ---------------- launch ------------------------------------------------
extern "C" void kernel_launch(void* const* d_in, const int* in_sizes, int n_in,
                              void* d_out, int out_size)
{
    const float* h   = (const float*)d_in[0];
    const float* wka = (const float*)d_in[1];
    const float* wkb = (const float*)d_in[2];
    const float* wza = (const float*)d_in[3];
    const float* wzb = (const float*)d_in[4];
    const float* ba  = (const float*)d_in[5];
    const float* bb  = (const float*)d_in[6];
    float* out = (float*)d_out;

    cudaFuncSetAttribute(gemm_kernel,
                         cudaFuncAttributeMaxDynamicSharedMemorySize, SMEM_BYTES);

    prep_w_kernel<<<dim3(D_ / 256, NCOL), 256>>>(wka, wkb, wza, wzb);
    gemm_kernel<<<(NTOK / BM) * (NCOL / BN), 512, SMEM_BYTES>>>(h);

    int dup = (out_size >= 2 * OUT_ELEMS) ? 1 : 0;
    epilogue_kernel<<<OUT_ELEMS / 256, 256>>>(ba, bb, out, dup);
}

// round 4
// speedup vs baseline: 5.1080x; 5.1080x over previous
#include <cuda_runtime.h>
#include <cuda_fp16.h>
#include <cstdint>

// ---------------- problem constants -------------------------------------
#define B_    4
#define S_    8192
#define D_    2048
#define HD_   128
#define NTOK  (B_ * S_)            // 32768 tokens
#define NCOL  512                  // 4 projections * HD
#define NBLK  (B_ * (S_ / 4))      // 8192 output blocks
#define OUT_ELEMS (NBLK * HD_)     // 1048576

// GEMM tiling
#define BM 128
#define BN 256
#define BK 32
#define NKC (D_ / BK)              // 64 k-chunks

// ---------------- scratch (static device globals) ------------------------
__device__ __half g_Wt[NCOL * D_];                // 2 MB, K-major fp16 weights
__device__ float  g_C[(size_t)NTOK * NCOL];       // 64 MB GEMM output

// ---------------- helpers ------------------------------------------------
__device__ __forceinline__ uint32_t smem_to_u32(const void* p) {
    uint32_t a;
    asm("{ .reg .u64 t; cvta.to.shared.u64 t, %1; cvt.u32.u64 %0, t; }"
        : "=r"(a) : "l"(p));
    return a;
}

// pack (k0, k1) -> f16x2 with k0 in the low half
__device__ __forceinline__ uint32_t pack2(float k0, float k1) {
    uint32_t r;
    asm("cvt.rn.f16x2.f32 %0, %1, %2;" : "=r"(r) : "f"(k1), "f"(k0));
    return r;
}

#define CP_ASYNC16(dst_u32, src_ptr) \
    asm volatile("cp.async.cg.shared.global [%0], [%1], 16;" \
                 :: "r"(dst_u32), "l"(src_ptr) : "memory")
#define CP_ASYNC_COMMIT() asm volatile("cp.async.commit_group;" ::: "memory")
#define CP_ASYNC_WAIT0()  asm volatile("cp.async.wait_group 0;" ::: "memory")

#define MMA_FP16(d, a, b) \
    asm volatile("mma.sync.aligned.m16n8k16.row.col.f32.f16.f16.f32 " \
                 "{%0,%1,%2,%3}, {%4,%5,%6,%7}, {%8,%9}, {%0,%1,%2,%3};" \
                 : "+f"((d)[0]), "+f"((d)[1]), "+f"((d)[2]), "+f"((d)[3]) \
                 : "r"((a)[0]), "r"((a)[1]), "r"((a)[2]), "r"((a)[3]), \
                   "r"((b)[0]), "r"((b)[1]))

// ---------------- smem layout (bytes): fp16 tiles, 64B rows padded to 80B
#define ROWB    80
#define A_PLANE (128 * ROWB)               // 10240 B
#define B_PLANE (256 * ROWB)               // 20480 B
#define STAGE   (A_PLANE + B_PLANE)        // 30720 B
#define OFF_A   0
#define OFF_B   A_PLANE
#define SMEM_BYTES (2 * STAGE)             // 61440 B

// ---------------- kernel 1: weight fp16 convert + transpose --------------
__global__ void prep_w_kernel(const float* __restrict__ wka,
                              const float* __restrict__ wkb,
                              const float* __restrict__ wza,
                              const float* __restrict__ wzb)
{
    int k = blockIdx.x * blockDim.x + threadIdx.x;   // 0..2047
    int n = blockIdx.y;                              // 0..511
    const float* w = (n < 128) ? wka : (n < 256) ? wkb : (n < 384) ? wza : wzb;
    int j = n & 127;
    g_Wt[(size_t)n * D_ + k] = __float2half_rn(w[(size_t)k * HD_ + j]);
}

// ---------------- kernel 2: pipelined fp16 mma.sync GEMM -----------------
// C[t, 0:512] = h[t, :] @ [Wkva | Wkvb | Wza | Wzb]
__global__ void __launch_bounds__(512, 1)
gemm_kernel(const float* __restrict__ h)
{
    extern __shared__ char sm[];
    const uint32_t smem_base = smem_to_u32(sm);

    const int tid    = threadIdx.x;
    const int lane   = tid & 31;
    const int wid    = tid >> 5;
    const int warp_m = wid >> 3;          // 0..1  (64 rows each)
    const int warp_n = wid & 7;           // 0..7  (32 cols each)

    const int t0 = (int)(blockIdx.x >> 1) * BM;
    const int n0 = (int)(blockIdx.x & 1) * BN;

    // A load coords: thread covers 8 contiguous k (2 float4), one row
    const int arow = tid >> 2;            // 0..127
    const int akc  = tid & 3;             // which 8-element k-chunk
    const float* hrow = h + (size_t)(t0 + arow) * D_ + akc * 8;
    const uint32_t a_sts = (uint32_t)(arow * ROWB + akc * 16);

    // B load coords: 2 x 16B cp.async per thread
    float4 v0, v1;

    // -------- prologue: stage 0 --------
    {
        v0 = *(const float4*)(hrow);
        v1 = *(const float4*)(hrow + 4);
        #pragma unroll
        for (int j = 0; j < 2; ++j) {
            int e = tid + j * 512;
            int row = e >> 2, kc = e & 3;
            uint32_t dst = smem_base + OFF_B + (uint32_t)(row * ROWB + kc * 16);
            CP_ASYNC16(dst, g_Wt + (size_t)(n0 + row) * D_ + kc * 8);
        }
        CP_ASYNC_COMMIT();
        uint4 q;
        q.x = pack2(v0.x, v0.y); q.y = pack2(v0.z, v0.w);
        q.z = pack2(v1.x, v1.y); q.w = pack2(v1.z, v1.w);
        *(uint4*)(sm + OFF_A + a_sts) = q;
        CP_ASYNC_WAIT0();
        __syncthreads();
    }

    float acc[4][4][4];
    #pragma unroll
    for (int mt = 0; mt < 4; ++mt)
        #pragma unroll
        for (int nt = 0; nt < 4; ++nt)
            #pragma unroll
            for (int i = 0; i < 4; ++i) acc[mt][nt][i] = 0.0f;

    const int fr = lane >> 2;             // fragment row within 8
    const int fco = (lane & 3) * 4;       // fragment k byte offset (2 fp16)

    for (int c = 0; c < NKC; ++c) {
        const int sb = (c & 1) * STAGE;
        const int nb = sb ^ STAGE;

        if (c + 1 < NKC) {
            const int k1 = (c + 1) * BK;
            v0 = *(const float4*)(hrow + k1);
            v1 = *(const float4*)(hrow + k1 + 4);
            #pragma unroll
            for (int j = 0; j < 2; ++j) {
                int e = tid + j * 512;
                int row = e >> 2, kc = e & 3;
                uint32_t dst = smem_base + nb + OFF_B + (uint32_t)(row * ROWB + kc * 16);
                CP_ASYNC16(dst, g_Wt + (size_t)(n0 + row) * D_ + k1 + kc * 8);
            }
            CP_ASYNC_COMMIT();
        }

        // -------- compute on stage sb: 2 k16-steps --------
        #pragma unroll
        for (int ks = 0; ks < 2; ++ks) {
            const int kb = ks * 32 + fco;          // byte offset within row
            uint32_t af[4][4], bf[4][2];
            #pragma unroll
            for (int mt = 0; mt < 4; ++mt) {
                const char* p = sm + sb + OFF_A + (warp_m * 64 + mt * 16 + fr) * ROWB + kb;
                af[mt][0] = *(const uint32_t*)(p);
                af[mt][1] = *(const uint32_t*)(p + 8 * ROWB);
                af[mt][2] = *(const uint32_t*)(p + 16);
                af[mt][3] = *(const uint32_t*)(p + 8 * ROWB + 16);
            }
            #pragma unroll
            for (int nt = 0; nt < 4; ++nt) {
                const char* p = sm + sb + OFF_B + (warp_n * 32 + nt * 8 + fr) * ROWB + kb;
                bf[nt][0] = *(const uint32_t*)(p);
                bf[nt][1] = *(const uint32_t*)(p + 16);
            }
            #pragma unroll
            for (int mt = 0; mt < 4; ++mt)
                #pragma unroll
                for (int nt = 0; nt < 4; ++nt)
                    MMA_FP16(acc[mt][nt], af[mt], bf[nt]);
        }

        if (c + 1 < NKC) {
            uint4 q;
            q.x = pack2(v0.x, v0.y); q.y = pack2(v0.z, v0.w);
            q.z = pack2(v1.x, v1.y); q.w = pack2(v1.z, v1.w);
            *(uint4*)(sm + nb + OFF_A + a_sts) = q;
            CP_ASYNC_WAIT0();
        }
        __syncthreads();
    }

    // -------- writeback --------
    #pragma unroll
    for (int mt = 0; mt < 4; ++mt) {
        int r0 = t0 + warp_m * 64 + mt * 16 + fr;
        #pragma unroll
        for (int nt = 0; nt < 4; ++nt) {
            int cb = n0 + warp_n * 32 + nt * 8 + (lane & 3) * 2;
            *(float2*)(g_C + (size_t)r0 * NCOL + cb) =
                make_float2(acc[mt][nt][0], acc[mt][nt][1]);
            *(float2*)(g_C + (size_t)(r0 + 8) * NCOL + cb) =
                make_float2(acc[mt][nt][2], acc[mt][nt][3]);
        }
    }
}

// ---------------- kernel 3: masked softmax compression -------------------
// C columns: [0,128)=c_a, [128,256)=c_b, [256,384)=z_a, [384,512)=z_b
__global__ void epilogue_kernel(const float* __restrict__ b_a,
                                const float* __restrict__ b_b,
                                float* __restrict__ out, int dup)
{
    int g  = blockIdx.x * blockDim.x + threadIdx.x;   // 0..1048575
    int d  = g & 127;
    int bi = g >> 7;           // global block id 0..8191
    int i  = bi & 2047;        // block within batch
    int b  = bi >> 11;         // batch
    int t0 = b * S_ + i * 4;   // first token of current block

    float logit[8], val[8];
    const bool has_prev = (i > 0);
    #pragma unroll
    for (int j = 0; j < 4; ++j) {
        if (has_prev) {
            const float* Cp = g_C + (size_t)(t0 - 4 + j) * NCOL;
            logit[j] = Cp[384 + d] + b_b[j * 128 + d];
            val[j]   = Cp[128 + d];
        } else {
            logit[j] = -3.0e38f;
            val[j]   = 0.0f;
        }
        const float* Cc = g_C + (size_t)(t0 + j) * NCOL;
        logit[4 + j] = Cc[256 + d] + b_a[j * 128 + d];
        val[4 + j]   = Cc[d];
    }
    float mx = logit[0];
    #pragma unroll
    for (int j = 1; j < 8; ++j) mx = fmaxf(mx, logit[j]);
    float s = 0.0f, acc = 0.0f;
    #pragma unroll
    for (int j = 0; j < 8; ++j) {
        float e = __expf(logit[j] - mx);
        s   += e;
        acc += e * val[j];
    }
    float r = acc / s;
    out[g] = r;
    if (dup) out[g + OUT_ELEMS] = r;
}

// ---------------- launch ------------------------------------------------
extern "C" void kernel_launch(void* const* d_in, const int* in_sizes, int n_in,
                              void* d_out, int out_size)
{
    const float* h   = (const float*)d_in[0];
    const float* wka = (const float*)d_in[1];
    const float* wkb = (const float*)d_in[2];
    const float* wza = (const float*)d_in[3];
    const float* wzb = (const float*)d_in[4];
    const float* ba  = (const float*)d_in[5];
    const float* bb  = (const float*)d_in[6];
    float* out = (float*)d_out;

    cudaFuncSetAttribute(gemm_kernel,
                         cudaFuncAttributeMaxDynamicSharedMemorySize, SMEM_BYTES);

    prep_w_kernel<<<dim3(D_ / 256, NCOL), 256>>>(wka, wkb, wza, wzb);
    gemm_kernel<<<(NTOK / BM) * (NCOL / BN), 512, SMEM_BYTES>>>(h);

    int dup = (out_size >= 2 * OUT_ELEMS) ? 1 : 0;
    epilogue_kernel<<<OUT_ELEMS / 256, 256>>>(ba, bb, out, dup);
}

// round 5
// speedup vs baseline: 5.4453x; 1.0660x over previous
#include <cuda_runtime.h>
#include <cuda_fp16.h>
#include <cstdint>

// ---------------- problem constants -------------------------------------
#define B_    4
#define S_    8192
#define D_    2048
#define HD_   128
#define NTOK  (B_ * S_)            // 32768 tokens
#define NCOL  512                  // 4 projections * HD
#define NBLK  (B_ * (S_ / 4))      // 8192 output blocks
#define OUT_ELEMS (NBLK * HD_)     // 1048576

// GEMM tiling
#define BM 64
#define BN 256
#define BK 32
#define NKC (D_ / BK)              // 64 k-chunks

// ---------------- scratch (static device globals) ------------------------
__device__ __half g_Wt[NCOL * D_];                // 2 MB, K-major fp16 weights
__device__ float  g_C[(size_t)NTOK * NCOL];       // 64 MB GEMM output

// ---------------- helpers ------------------------------------------------
__device__ __forceinline__ uint32_t smem_to_u32(const void* p) {
    uint32_t a;
    asm("{ .reg .u64 t; cvta.to.shared.u64 t, %1; cvt.u32.u64 %0, t; }"
        : "=r"(a) : "l"(p));
    return a;
}

// pack (k0, k1) -> f16x2 with k0 in the low half
__device__ __forceinline__ uint32_t pack2(float k0, float k1) {
    uint32_t r;
    asm("cvt.rn.f16x2.f32 %0, %1, %2;" : "=r"(r) : "f"(k1), "f"(k0));
    return r;
}

#define CP_ASYNC16(dst_u32, src_ptr) \
    asm volatile("cp.async.cg.shared.global [%0], [%1], 16;" \
                 :: "r"(dst_u32), "l"(src_ptr) : "memory")
#define CP_ASYNC_COMMIT() asm volatile("cp.async.commit_group;" ::: "memory")
#define CP_ASYNC_WAIT0()  asm volatile("cp.async.wait_group 0;" ::: "memory")

#define MMA_FP16(d, a, b) \
    asm volatile("mma.sync.aligned.m16n8k16.row.col.f32.f16.f16.f32 " \
                 "{%0,%1,%2,%3}, {%4,%5,%6,%7}, {%8,%9}, {%0,%1,%2,%3};" \
                 : "+f"((d)[0]), "+f"((d)[1]), "+f"((d)[2]), "+f"((d)[3]) \
                 : "r"((a)[0]), "r"((a)[1]), "r"((a)[2]), "r"((a)[3]), \
                   "r"((b)[0]), "r"((b)[1]))

// ---------------- smem layout (bytes): fp16 tiles, 64B rows padded to 80B
#define ROWB    80
#define A_PLANE (64 * ROWB)                // 5120 B
#define B_PLANE (256 * ROWB)               // 20480 B
#define STAGE   (A_PLANE + B_PLANE)        // 25600 B
#define OFF_A   0
#define OFF_B   A_PLANE
#define SMEM_BYTES (2 * STAGE)             // 51200 B

// ---------------- kernel 1: coalesced fp16 transpose of weights ----------
// g_Wt[n, k] = w_mat[k, j],  n = mat*128 + j
__global__ void prep_w_kernel(const float* __restrict__ wka,
                              const float* __restrict__ wkb,
                              const float* __restrict__ wza,
                              const float* __restrict__ wzb)
{
    __shared__ float tile[32][33];
    const int mat = blockIdx.z;
    const float* w = (mat == 0) ? wka : (mat == 1) ? wkb : (mat == 2) ? wza : wzb;
    const int k0 = blockIdx.x * 32;
    const int j0 = blockIdx.y * 32;
    const int tx = threadIdx.x;       // 0..31
    const int ty = threadIdx.y;       // 0..7

    #pragma unroll
    for (int i = 0; i < 32; i += 8)
        tile[ty + i][tx] = w[(size_t)(k0 + ty + i) * HD_ + j0 + tx];
    __syncthreads();
    #pragma unroll
    for (int i = 0; i < 32; i += 8)
        g_Wt[(size_t)(mat * HD_ + j0 + ty + i) * D_ + k0 + tx] =
            __float2half_rn(tile[tx][ty + i]);
}

// ---------------- kernel 2: pipelined fp16 mma.sync GEMM -----------------
// C[t, 0:512] = h[t, :] @ [Wkva | Wkvb | Wza | Wzb]
__global__ void __launch_bounds__(256, 2)
gemm_kernel(const float* __restrict__ h)
{
    extern __shared__ char sm[];
    const uint32_t smem_base = smem_to_u32(sm);

    const int tid    = threadIdx.x;
    const int lane   = tid & 31;
    const int wid    = tid >> 5;
    const int warp_m = wid >> 2;          // 0..1  (32 rows each)
    const int warp_n = wid & 3;           // 0..3  (64 cols each)

    const int t0 = (int)(blockIdx.x >> 1) * BM;
    const int n0 = (int)(blockIdx.x & 1) * BN;

    // A load coords: thread covers 8 contiguous k, one row
    const int arow = tid >> 2;            // 0..63
    const int akc  = tid & 3;             // which 8-element k-chunk
    const float* hrow = h + (size_t)(t0 + arow) * D_ + akc * 8;
    const uint32_t a_sts = (uint32_t)(arow * ROWB + akc * 16);

    float4 v0, v1;

    // -------- prologue: stage 0 --------
    {
        v0 = *(const float4*)(hrow);
        v1 = *(const float4*)(hrow + 4);
        #pragma unroll
        for (int j = 0; j < 4; ++j) {
            int e = tid + j * 256;
            int row = e >> 2, kc = e & 3;
            uint32_t dst = smem_base + OFF_B + (uint32_t)(row * ROWB + kc * 16);
            CP_ASYNC16(dst, g_Wt + (size_t)(n0 + row) * D_ + kc * 8);
        }
        CP_ASYNC_COMMIT();
        uint4 q;
        q.x = pack2(v0.x, v0.y); q.y = pack2(v0.z, v0.w);
        q.z = pack2(v1.x, v1.y); q.w = pack2(v1.z, v1.w);
        *(uint4*)(sm + OFF_A + a_sts) = q;
        CP_ASYNC_WAIT0();
        __syncthreads();
    }

    float acc[2][8][4];
    #pragma unroll
    for (int mt = 0; mt < 2; ++mt)
        #pragma unroll
        for (int nt = 0; nt < 8; ++nt)
            #pragma unroll
            for (int i = 0; i < 4; ++i) acc[mt][nt][i] = 0.0f;

    const int fr  = lane >> 2;            // fragment row within 8
    const int fco = (lane & 3) * 4;       // fragment k byte offset (2 fp16)

    for (int c = 0; c < NKC; ++c) {
        const int sb = (c & 1) * STAGE;
        const int nb = sb ^ STAGE;

        if (c + 1 < NKC) {
            const int k1 = (c + 1) * BK;
            v0 = *(const float4*)(hrow + k1);
            v1 = *(const float4*)(hrow + k1 + 4);
            #pragma unroll
            for (int j = 0; j < 4; ++j) {
                int e = tid + j * 256;
                int row = e >> 2, kc = e & 3;
                uint32_t dst = smem_base + nb + OFF_B + (uint32_t)(row * ROWB + kc * 16);
                CP_ASYNC16(dst, g_Wt + (size_t)(n0 + row) * D_ + k1 + kc * 8);
            }
            CP_ASYNC_COMMIT();
        }

        // -------- compute on stage sb: 2 k16-steps --------
        #pragma unroll
        for (int ks = 0; ks < 2; ++ks) {
            const int kb = ks * 32 + fco;          // byte offset within row
            uint32_t af[2][4], bf[8][2];
            #pragma unroll
            for (int mt = 0; mt < 2; ++mt) {
                const char* p = sm + sb + OFF_A + (warp_m * 32 + mt * 16 + fr) * ROWB + kb;
                af[mt][0] = *(const uint32_t*)(p);
                af[mt][1] = *(const uint32_t*)(p + 8 * ROWB);
                af[mt][2] = *(const uint32_t*)(p + 16);
                af[mt][3] = *(const uint32_t*)(p + 8 * ROWB + 16);
            }
            #pragma unroll
            for (int nt = 0; nt < 8; ++nt) {
                const char* p = sm + sb + OFF_B + (warp_n * 64 + nt * 8 + fr) * ROWB + kb;
                bf[nt][0] = *(const uint32_t*)(p);
                bf[nt][1] = *(const uint32_t*)(p + 16);
            }
            #pragma unroll
            for (int mt = 0; mt < 2; ++mt)
                #pragma unroll
                for (int nt = 0; nt < 8; ++nt)
                    MMA_FP16(acc[mt][nt], af[mt], bf[nt]);
        }

        if (c + 1 < NKC) {
            uint4 q;
            q.x = pack2(v0.x, v0.y); q.y = pack2(v0.z, v0.w);
            q.z = pack2(v1.x, v1.y); q.w = pack2(v1.z, v1.w);
            *(uint4*)(sm + nb + OFF_A + a_sts) = q;
            CP_ASYNC_WAIT0();
        }
        __syncthreads();
    }

    // -------- writeback --------
    #pragma unroll
    for (int mt = 0; mt < 2; ++mt) {
        int r0 = t0 + warp_m * 32 + mt * 16 + fr;
        #pragma unroll
        for (int nt = 0; nt < 8; ++nt) {
            int cb = n0 + warp_n * 64 + nt * 8 + (lane & 3) * 2;
            *(float2*)(g_C + (size_t)r0 * NCOL + cb) =
                make_float2(acc[mt][nt][0], acc[mt][nt][1]);
            *(float2*)(g_C + (size_t)(r0 + 8) * NCOL + cb) =
                make_float2(acc[mt][nt][2], acc[mt][nt][3]);
        }
    }
}

// ---------------- kernel 3: masked softmax compression -------------------
// C columns: [0,128)=c_a, [128,256)=c_b, [256,384)=z_a, [384,512)=z_b
__global__ void epilogue_kernel(const float* __restrict__ b_a,
                                const float* __restrict__ b_b,
                                float* __restrict__ out, int dup)
{
    int g  = blockIdx.x * blockDim.x + threadIdx.x;   // 0..1048575
    int d  = g & 127;
    int bi = g >> 7;           // global block id 0..8191
    int i  = bi & 2047;        // block within batch
    int b  = bi >> 11;         // batch
    int t0 = b * S_ + i * 4;   // first token of current block

    float logit[8], val[8];
    const bool has_prev = (i > 0);
    #pragma unroll
    for (int j = 0; j < 4; ++j) {
        if (has_prev) {
            const float* Cp = g_C + (size_t)(t0 - 4 + j) * NCOL;
            logit[j] = Cp[384 + d] + b_b[j * 128 + d];
            val[j]   = Cp[128 + d];
        } else {
            logit[j] = -3.0e38f;
            val[j]   = 0.0f;
        }
        const float* Cc = g_C + (size_t)(t0 + j) * NCOL;
        logit[4 + j] = Cc[256 + d] + b_a[j * 128 + d];
        val[4 + j]   = Cc[d];
    }
    float mx = logit[0];
    #pragma unroll
    for (int j = 1; j < 8; ++j) mx = fmaxf(mx, logit[j]);
    float s = 0.0f, acc = 0.0f;
    #pragma unroll
    for (int j = 0; j < 8; ++j) {
        float e = __expf(logit[j] - mx);
        s   += e;
        acc += e * val[j];
    }
    float r = acc / s;
    out[g] = r;
    if (dup) out[g + OUT_ELEMS] = r;
}

// ---------------- launch ------------------------------------------------
extern "C" void kernel_launch(void* const* d_in, const int* in_sizes, int n_in,
                              void* d_out, int out_size)
{
    const float* h   = (const float*)d_in[0];
    const float* wka = (const float*)d_in[1];
    const float* wkb = (const float*)d_in[2];
    const float* wza = (const float*)d_in[3];
    const float* wzb = (const float*)d_in[4];
    const float* ba  = (const float*)d_in[5];
    const float* bb  = (const float*)d_in[6];
    float* out = (float*)d_out;

    cudaFuncSetAttribute(gemm_kernel,
                         cudaFuncAttributeMaxDynamicSharedMemorySize, SMEM_BYTES);

    prep_w_kernel<<<dim3(D_ / 32, HD_ / 32, 4), dim3(32, 8)>>>(wka, wkb, wza, wzb);
    gemm_kernel<<<(NTOK / BM) * (NCOL / BN), 256, SMEM_BYTES>>>(h);

    int dup = (out_size >= 2 * OUT_ELEMS) ? 1 : 0;
    epilogue_kernel<<<OUT_ELEMS / 256, 256>>>(ba, bb, out, dup);
}

// round 6
// speedup vs baseline: 5.4470x; 1.0003x over previous
#include <cuda_runtime.h>
#include <cuda_fp16.h>
#include <cstdint>

// ---------------- problem constants -------------------------------------
#define B_    4
#define S_    8192
#define D_    2048
#define HD_   128
#define NTOK  (B_ * S_)            // 32768 tokens
#define NCOL  512                  // 4 projections * HD
#define NBLK  (B_ * (S_ / 4))      // 8192 output blocks
#define OUT_ELEMS (NBLK * HD_)     // 1048576

// GEMM tiling
#define BM 64
#define BN 256
#define BK 64
#define NKC (D_ / BK)              // 32 k-chunks

// ---------------- scratch (static device globals) ------------------------
__device__ __half g_Wt[NCOL * D_];                // 2 MB, K-major fp16 weights
__device__ __half g_C[(size_t)NTOK * NCOL];       // 32 MB GEMM output (fp16)

// ---------------- helpers ------------------------------------------------
__device__ __forceinline__ uint32_t smem_to_u32(const void* p) {
    uint32_t a;
    asm("{ .reg .u64 t; cvta.to.shared.u64 t, %1; cvt.u32.u64 %0, t; }"
        : "=r"(a) : "l"(p));
    return a;
}

// pack (k0, k1) -> f16x2 with k0 in the low half
__device__ __forceinline__ uint32_t pack2(float k0, float k1) {
    uint32_t r;
    asm("cvt.rn.f16x2.f32 %0, %1, %2;" : "=r"(r) : "f"(k1), "f"(k0));
    return r;
}

#define CP_ASYNC16(dst_u32, src_ptr) \
    asm volatile("cp.async.cg.shared.global [%0], [%1], 16;" \
                 :: "r"(dst_u32), "l"(src_ptr) : "memory")
#define CP_ASYNC_COMMIT() asm volatile("cp.async.commit_group;" ::: "memory")
#define CP_ASYNC_WAIT0()  asm volatile("cp.async.wait_group 0;" ::: "memory")

#define MMA_FP16(d, a, b) \
    asm volatile("mma.sync.aligned.m16n8k16.row.col.f32.f16.f16.f32 " \
                 "{%0,%1,%2,%3}, {%4,%5,%6,%7}, {%8,%9}, {%0,%1,%2,%3};" \
                 : "+f"((d)[0]), "+f"((d)[1]), "+f"((d)[2]), "+f"((d)[3]) \
                 : "r"((a)[0]), "r"((a)[1]), "r"((a)[2]), "r"((a)[3]), \
                   "r"((b)[0]), "r"((b)[1]))

// ---------------- smem layout (bytes): fp16 tiles, 128B rows padded to 144B
#define ROWB    144
#define A_PLANE (64 * ROWB)                // 9216 B
#define B_PLANE (256 * ROWB)               // 36864 B
#define STAGE   (A_PLANE + B_PLANE)        // 46080 B
#define OFF_A   0
#define OFF_B   A_PLANE
#define SMEM_BYTES (2 * STAGE)             // 92160 B

// ---------------- kernel 1: coalesced fp16 transpose of weights ----------
// g_Wt[n, k] = w_mat[k, j],  n = mat*128 + j
__global__ void prep_w_kernel(const float* __restrict__ wka,
                              const float* __restrict__ wkb,
                              const float* __restrict__ wza,
                              const float* __restrict__ wzb)
{
    __shared__ float tile[32][33];
    const int mat = blockIdx.z;
    const float* w = (mat == 0) ? wka : (mat == 1) ? wkb : (mat == 2) ? wza : wzb;
    const int k0 = blockIdx.x * 32;
    const int j0 = blockIdx.y * 32;
    const int tx = threadIdx.x;       // 0..31
    const int ty = threadIdx.y;       // 0..7

    #pragma unroll
    for (int i = 0; i < 32; i += 8)
        tile[ty + i][tx] = w[(size_t)(k0 + ty + i) * HD_ + j0 + tx];
    __syncthreads();
    #pragma unroll
    for (int i = 0; i < 32; i += 8)
        g_Wt[(size_t)(mat * HD_ + j0 + ty + i) * D_ + k0 + tx] =
            __float2half_rn(tile[tx][ty + i]);
}

// ---------------- kernel 2: pipelined fp16 mma.sync GEMM -----------------
// C[t, 0:512] = h[t, :] @ [Wkva | Wkvb | Wza | Wzb]
__global__ void __launch_bounds__(256, 2)
gemm_kernel(const float* __restrict__ h)
{
    extern __shared__ char sm[];
    const uint32_t smem_base = smem_to_u32(sm);

    const int tid    = threadIdx.x;
    const int lane   = tid & 31;
    const int wid    = tid >> 5;
    const int warp_m = wid >> 2;          // 0..1  (32 rows each)
    const int warp_n = wid & 3;           // 0..3  (64 cols each)

    const int t0 = (int)(blockIdx.x >> 1) * BM;
    const int n0 = (int)(blockIdx.x & 1) * BN;

    // A load coords: thread covers 16 contiguous k, one row
    const int arow = tid >> 2;            // 0..63
    const int akc  = tid & 3;             // 16-element k-chunk within 64
    const float* hrow = h + (size_t)(t0 + arow) * D_ + akc * 16;
    const uint32_t a_sts = (uint32_t)(arow * ROWB + akc * 32);

    // B load coords: 8 x 16B cp.async per thread per chunk
    const int brow = tid >> 3;            // base pattern via e = tid + j*256
    (void)brow;

    uint32_t qa[8];

    // quantize 16 floats from hrow+off into qa
    auto loadquantA = [&](int koff) {
        #pragma unroll
        for (int i = 0; i < 4; ++i) {
            float4 v = *(const float4*)(hrow + koff + i * 4);
            qa[2 * i]     = pack2(v.x, v.y);
            qa[2 * i + 1] = pack2(v.z, v.w);
        }
    };

    // -------- prologue: stage 0 --------
    {
        loadquantA(0);
        #pragma unroll
        for (int j = 0; j < 8; ++j) {
            int e = tid + j * 256;
            int row = e >> 3, kc = e & 7;
            uint32_t dst = smem_base + OFF_B + (uint32_t)(row * ROWB + kc * 16);
            CP_ASYNC16(dst, g_Wt + (size_t)(n0 + row) * D_ + kc * 8);
        }
        CP_ASYNC_COMMIT();
        *(uint4*)(sm + OFF_A + a_sts)      = *(uint4*)(qa);
        *(uint4*)(sm + OFF_A + a_sts + 16) = *(uint4*)(qa + 4);
        CP_ASYNC_WAIT0();
        __syncthreads();
    }

    float acc[2][8][4];
    #pragma unroll
    for (int mt = 0; mt < 2; ++mt)
        #pragma unroll
        for (int nt = 0; nt < 8; ++nt)
            #pragma unroll
            for (int i = 0; i < 4; ++i) acc[mt][nt][i] = 0.0f;

    const int fr  = lane >> 2;            // fragment row within 8
    const int fco = (lane & 3) * 4;       // fragment k byte offset (2 fp16)

    for (int c = 0; c < NKC; ++c) {
        const int sb = (c & 1) * STAGE;
        const int nb = sb ^ STAGE;

        if (c + 1 < NKC) {
            const int k1 = (c + 1) * BK;
            loadquantA(k1);
            #pragma unroll
            for (int j = 0; j < 8; ++j) {
                int e = tid + j * 256;
                int row = e >> 3, kc = e & 7;
                uint32_t dst = smem_base + nb + OFF_B + (uint32_t)(row * ROWB + kc * 16);
                CP_ASYNC16(dst, g_Wt + (size_t)(n0 + row) * D_ + k1 + kc * 8);
            }
            CP_ASYNC_COMMIT();
        }

        // -------- compute on stage sb: 4 k16-steps --------
        #pragma unroll
        for (int ks = 0; ks < 4; ++ks) {
            const int kb = ks * 32 + fco;          // byte offset within row
            uint32_t af[2][4], bf[8][2];
            #pragma unroll
            for (int mt = 0; mt < 2; ++mt) {
                const char* p = sm + sb + OFF_A + (warp_m * 32 + mt * 16 + fr) * ROWB + kb;
                af[mt][0] = *(const uint32_t*)(p);
                af[mt][1] = *(const uint32_t*)(p + 8 * ROWB);
                af[mt][2] = *(const uint32_t*)(p + 16);
                af[mt][3] = *(const uint32_t*)(p + 8 * ROWB + 16);
            }
            #pragma unroll
            for (int nt = 0; nt < 8; ++nt) {
                const char* p = sm + sb + OFF_B + (warp_n * 64 + nt * 8 + fr) * ROWB + kb;
                bf[nt][0] = *(const uint32_t*)(p);
                bf[nt][1] = *(const uint32_t*)(p + 16);
            }
            #pragma unroll
            for (int mt = 0; mt < 2; ++mt)
                #pragma unroll
                for (int nt = 0; nt < 8; ++nt)
                    MMA_FP16(acc[mt][nt], af[mt], bf[nt]);
        }

        if (c + 1 < NKC) {
            *(uint4*)(sm + nb + OFF_A + a_sts)      = *(uint4*)(qa);
            *(uint4*)(sm + nb + OFF_A + a_sts + 16) = *(uint4*)(qa + 4);
            CP_ASYNC_WAIT0();
        }
        __syncthreads();
    }

    // -------- writeback (fp16) --------
    #pragma unroll
    for (int mt = 0; mt < 2; ++mt) {
        int r0 = t0 + warp_m * 32 + mt * 16 + fr;
        #pragma unroll
        for (int nt = 0; nt < 8; ++nt) {
            int cb = n0 + warp_n * 64 + nt * 8 + (lane & 3) * 2;
            *(uint32_t*)(g_C + (size_t)r0 * NCOL + cb) =
                pack2(acc[mt][nt][0], acc[mt][nt][1]);
            *(uint32_t*)(g_C + (size_t)(r0 + 8) * NCOL + cb) =
                pack2(acc[mt][nt][2], acc[mt][nt][3]);
        }
    }
}

// ---------------- kernel 3: masked softmax compression -------------------
// C columns: [0,128)=c_a, [128,256)=c_b, [256,384)=z_a, [384,512)=z_b
__global__ void epilogue_kernel(const float* __restrict__ b_a,
                                const float* __restrict__ b_b,
                                float* __restrict__ out, int dup)
{
    int g  = blockIdx.x * blockDim.x + threadIdx.x;   // 0..1048575
    int d  = g & 127;
    int bi = g >> 7;           // global block id 0..8191
    int i  = bi & 2047;        // block within batch
    int b  = bi >> 11;         // batch
    int t0 = b * S_ + i * 4;   // first token of current block

    float logit[8], val[8];
    const bool has_prev = (i > 0);
    #pragma unroll
    for (int j = 0; j < 4; ++j) {
        if (has_prev) {
            const __half* Cp = g_C + (size_t)(t0 - 4 + j) * NCOL;
            logit[j] = __half2float(Cp[384 + d]) + b_b[j * 128 + d];
            val[j]   = __half2float(Cp[128 + d]);
        } else {
            logit[j] = -3.0e38f;
            val[j]   = 0.0f;
        }
        const __half* Cc = g_C + (size_t)(t0 + j) * NCOL;
        logit[4 + j] = __half2float(Cc[256 + d]) + b_a[j * 128 + d];
        val[4 + j]   = __half2float(Cc[d]);
    }
    float mx = logit[0];
    #pragma unroll
    for (int j = 1; j < 8; ++j) mx = fmaxf(mx, logit[j]);
    float s = 0.0f, acc = 0.0f;
    #pragma unroll
    for (int j = 0; j < 8; ++j) {
        float e = __expf(logit[j] - mx);
        s   += e;
        acc += e * val[j];
    }
    float r = acc / s;
    out[g] = r;
    if (dup) out[g + OUT_ELEMS] = r;
}

// ---------------- launch ------------------------------------------------
extern "C" void kernel_launch(void* const* d_in, const int* in_sizes, int n_in,
                              void* d_out, int out_size)
{
    const float* h   = (const float*)d_in[0];
    const float* wka = (const float*)d_in[1];
    const float* wkb = (const float*)d_in[2];
    const float* wza = (const float*)d_in[3];
    const float* wzb = (const float*)d_in[4];
    const float* ba  = (const float*)d_in[5];
    const float* bb  = (const float*)d_in[6];
    float* out = (float*)d_out;

    cudaFuncSetAttribute(gemm_kernel,
                         cudaFuncAttributeMaxDynamicSharedMemorySize, SMEM_BYTES);

    prep_w_kernel<<<dim3(D_ / 32, HD_ / 32, 4), dim3(32, 8)>>>(wka, wkb, wza, wzb);
    gemm_kernel<<<(NTOK / BM) * (NCOL / BN), 256, SMEM_BYTES>>>(h);

    int dup = (out_size >= 2 * OUT_ELEMS) ? 1 : 0;
    epilogue_kernel<<<OUT_ELEMS / 256, 256>>>(ba, bb, out, dup);
}